// round 7
// baseline (speedup 1.0000x reference)
#include <cuda_runtime.h>

// Batched OSQP ADMM: B=64, n=256, m=512, 200 iterations.
// Pipeline: syrk(M = rho*A'A + diag(P)+sigma) -> Cholesky (col-major, in place)
//   -> transpose L -> blocked fwd/bwd identity solves -> Minv
//   -> persistent ADMM kernel, 1 CTA per batch, 200 iters fully on-chip,
//      192KB of Minv cached in SMEM, float4-coalesced GEMVs with smem reductions.

#define NBAT 64
#define NV   256
#define MCON 512

__device__ float g_M   [(size_t)NBAT*NV*NV];    // M, then L (col-major lower)
__device__ float g_W   [(size_t)NBAT*NV*NV];    // L row-major (transpose of g_M)
__device__ float g_Minv[(size_t)NBAT*NV*NV];    // M^{-1}, row-major
__device__ float g_At  [(size_t)NBAT*NV*MCON];  // A^T: At[j*512+m] = A[m*256+j]

__device__ __forceinline__ void fma4(float4& a, const float4 v, const float s) {
    a.x = fmaf(v.x, s, a.x); a.y = fmaf(v.y, s, a.y);
    a.z = fmaf(v.z, s, a.z); a.w = fmaf(v.w, s, a.w);
}

// ---------------------------------------------------------------------------
// syrk: g_M[b] = RHO * A^T A + diag(P + SIGMA). 64x64 tiles, upper pairs with
// mirrored writes. 256 threads, 4x4 register micro-tile, BK=16.
// ---------------------------------------------------------------------------
__global__ void __launch_bounds__(256) syrk_kernel(const float* __restrict__ A,
                                                   const float* __restrict__ P)
{
    const int pr = blockIdx.x, b = blockIdx.y;
    int ti, tj;
    if      (pr < 4) { ti = 0; tj = pr;     }
    else if (pr < 7) { ti = 1; tj = pr - 3; }
    else if (pr < 9) { ti = 2; tj = pr - 5; }
    else             { ti = 3; tj = 3;      }

    __shared__ float As[16 * 64], Bs[16 * 64];
    const float* Ab = A + (size_t)b * MCON * NV;
    const int tid = threadIdx.x, lr = tid >> 4, lc = tid & 15;

    float acc[4][4] = {};
    for (int k0 = 0; k0 < MCON; k0 += 16) {
        *(float4*)(As + lr*64 + lc*4) = *(const float4*)(Ab + (size_t)(k0+lr)*NV + ti*64 + lc*4);
        *(float4*)(Bs + lr*64 + lc*4) = *(const float4*)(Ab + (size_t)(k0+lr)*NV + tj*64 + lc*4);
        __syncthreads();
#pragma unroll
        for (int kk = 0; kk < 16; kk++) {
            float4 a4 = *(float4*)(As + kk*64 + lr*4);
            float4 b4 = *(float4*)(Bs + kk*64 + lc*4);
            float av[4] = {a4.x, a4.y, a4.z, a4.w};
            float bv[4] = {b4.x, b4.y, b4.z, b4.w};
#pragma unroll
            for (int r = 0; r < 4; r++)
#pragma unroll
                for (int s = 0; s < 4; s++)
                    acc[r][s] = fmaf(av[r], bv[s], acc[r][s]);
        }
        __syncthreads();
    }

    float* Mb = g_M + (size_t)b * NV * NV;
    const float RHO = 0.1f, SIGMA = 1e-6f;
#pragma unroll
    for (int r = 0; r < 4; r++)
#pragma unroll
        for (int s = 0; s < 4; s++) {
            int i = ti*64 + lr*4 + r;
            int j = tj*64 + lc*4 + s;
            float v = RHO * acc[r][s];
            if (i == j) v += P[b*NV + i] + SIGMA;
            Mb[(size_t)i*NV + j] = v;
            if (ti != tj) Mb[(size_t)j*NV + i] = v;
        }
}

// ---------------------------------------------------------------------------
// Batched 32x32 tiled transpose: dst[c][r] = src[r][c], src is R x C row-major.
// ---------------------------------------------------------------------------
__global__ void transpose_kernel(const float* __restrict__ src, float* __restrict__ dst,
                                 int R, int C)
{
    __shared__ float t[32][33];
    const size_t off = (size_t)blockIdx.z * R * C;
    const int c0 = blockIdx.x * 32, r0 = blockIdx.y * 32;
    const int tx = threadIdx.x, ty = threadIdx.y;   // 32 x 8
#pragma unroll
    for (int k = 0; k < 32; k += 8)
        t[ty + k][tx] = src[off + (size_t)(r0 + ty + k) * C + c0 + tx];
    __syncthreads();
#pragma unroll
    for (int k = 0; k < 32; k += 8)
        dst[off + (size_t)(c0 + ty + k) * R + r0 + tx] = t[tx][ty + k];
}

// ---------------------------------------------------------------------------
// Cholesky, left-looking, col-major (g_M row i is column i of L), in place.
// One block per batch, 256 threads; first 192 columns cached in SMEM.
// ---------------------------------------------------------------------------
__global__ void __launch_bounds__(256) chol_kernel()
{
    const int b = blockIdx.x, tid = threadIdx.x;
    float* M = g_M + (size_t)b * NV * NV;
    extern __shared__ float Lc[];      // 192*256 floats
    __shared__ float sdiag;

    for (int j = 0; j < NV; j++) {
        float acc = M[(size_t)j*NV + tid];
        const int kc = j < 192 ? j : 192;
#pragma unroll 4
        for (int k = 0; k < kc; k++)
            acc -= Lc[k*NV + tid] * Lc[k*NV + j];
        for (int k = 192; k < j; k++)
            acc -= M[(size_t)k*NV + tid] * M[(size_t)k*NV + j];
        if (tid == j) sdiag = acc;
        __syncthreads();
        float val = acc * rsqrtf(sdiag);
        if (tid >= j) {
            M[(size_t)j*NV + tid] = val;
            if (j < 192) Lc[j*NV + tid] = val;
        }
        __syncthreads();
    }
}

// ---------------------------------------------------------------------------
// Minv: block (g, b) computes 64 columns [c0, c0+64) of M^{-1} by solving
// L y = e (fwd, update form, column reads of L = g_M rows) then L^T x = y
// (bwd, row reads of L = g_W rows). Y (256x64) and a 64-row L panel in SMEM.
// Thread map: q8 = tid>>5 strides rows by 8, c2 = tid&31 owns a float2 of cols.
// ---------------------------------------------------------------------------
__global__ void __launch_bounds__(256) minv_kernel()
{
    const int g = blockIdx.x, b = blockIdx.y, tid = threadIdx.x;
    const int c0 = g * 64;
    extern __shared__ float sm[];
    float* Yf    = sm;            // 16384 floats
    float* Lp    = sm + 16384;    // 16384 floats
    float* rdiag = sm + 32768;    // 256 floats
    const float* M  = g_M + (size_t)b * NV * NV;
    const float* Wt = g_W + (size_t)b * NV * NV;

    rdiag[tid] = 1.0f / M[(size_t)tid*NV + tid];
    for (int idx = tid; idx < 16384; idx += 256) Yf[idx] = 0.0f;
    __syncthreads();
    if (tid < 64) Yf[(c0 + tid)*64 + tid] = 1.0f;
    __syncthreads();

    const int q8 = tid >> 5, c2 = tid & 31;
    float2* Y2 = (float2*)Yf;

    // forward: L y = e   (rows < c0 identically zero -> start at c0)
    for (int i = c0; i < NV; i++) {
        if ((i & 63) == 0) {
            for (int idx = tid; idx < 16384; idx += 256)
                Lp[idx] = M[(size_t)(i + (idx >> 8)) * NV + (idx & 255)];
            __syncthreads();
        }
        if (tid < 64) Yf[i*64 + tid] *= rdiag[i];
        __syncthreads();
        float2 yv = Y2[i*32 + c2];
        const int p = i & ~63;
        const float* lcol = Lp + (i - p) * NV;
        for (int i2 = i + 1 + ((q8 - (i + 1)) & 7); i2 < NV; i2 += 8) {
            float lv = lcol[i2];
            float2 t = Y2[i2*32 + c2];
            t.x = fmaf(-lv, yv.x, t.x);
            t.y = fmaf(-lv, yv.y, t.y);
            Y2[i2*32 + c2] = t;
        }
        __syncthreads();
    }

    // backward: L^T x = y
    for (int i = NV - 1; i >= 0; i--) {
        if ((i & 63) == 63) {
            const int p = i - 63;
            for (int idx = tid; idx < 16384; idx += 256)
                Lp[idx] = Wt[(size_t)(p + (idx >> 8)) * NV + (idx & 255)];
            __syncthreads();
        }
        if (tid < 64) Yf[i*64 + tid] *= rdiag[i];
        __syncthreads();
        float2 xv = Y2[i*32 + c2];
        const int p = i & ~63;
        const float* lrow = Lp + (i - p) * NV;
        for (int i2 = q8; i2 < i; i2 += 8) {
            float lv = lrow[i2];
            float2 t = Y2[i2*32 + c2];
            t.x = fmaf(-lv, xv.x, t.x);
            t.y = fmaf(-lv, xv.y, t.y);
            Y2[i2*32 + c2] = t;
        }
        __syncthreads();
    }

    float* Mi = g_Minv + (size_t)b * NV * NV;
    for (int idx = tid; idx < 16384; idx += 256)
        Mi[(size_t)(idx >> 6) * NV + c0 + (idx & 63)] = Yf[idx];
}

// ---------------------------------------------------------------------------
// ADMM: one CTA per batch, 256 threads, 200 iterations on-chip.
// SMEM: Minv rows [0,192) cached (192KB) + state vectors + reduction buffer.
// All GEMVs: float4 coalesced loads, warp-uniform smem broadcast operand,
// split-K partials reduced through smem.
// ---------------------------------------------------------------------------
__global__ void __launch_bounds__(256, 1) admm_kernel(const float* __restrict__ A,
                                                      const float* __restrict__ q,
                                                      const float* __restrict__ l,
                                                      const float* __restrict__ u,
                                                      float* __restrict__ out)
{
    const int b = blockIdx.x, tid = threadIdx.x;
    extern __shared__ float sh[];
    float* Mc    = sh;            // 49152 floats (Minv rows 0..191)
    float* z_s   = sh + 49152;    // 512
    float* y_s   = sh + 49664;    // 512
    float* w_s   = sh + 50176;    // 512
    float* rhs_s = sh + 50688;    // 256
    float* xt_s  = sh + 50944;    // 256
    float* xs    = sh + 51200;    // 256
    float* qs    = sh + 51456;    // 256
    float* red   = sh + 51712;    // 1024

    const float SIGMA = 1e-6f, RHO = 0.1f, ALPHA = 1.6f;
    const float* Ab  = A      + (size_t)b * MCON * NV;
    const float* Atb = g_At   + (size_t)b * NV * MCON;
    const float* Mb  = g_Minv + (size_t)b * NV * NV;

    for (int idx = tid; idx < 12288; idx += 256)
        ((float4*)Mc)[idx] = ((const float4*)Mb)[idx];
    z_s[tid] = 0.0f; z_s[tid + 256] = 0.0f;
    y_s[tid] = 0.0f; y_s[tid + 256] = 0.0f;
    xs[tid] = 0.0f;  qs[tid] = q[b*NV + tid];
    const float l0 = l[b*MCON + tid], l1 = l[b*MCON + tid + 256];
    const float u0 = u[b*MCON + tid], u1 = u[b*MCON + tid + 256];
    __syncthreads();

    const int ms = tid >> 6, jg = tid & 63;      // GEMV1/2 map
    const int js = tid >> 7, mq = tid & 127;     // GEMV3 map

    for (int it = 0; it < 200; it++) {
        // w = rho*z - y
        w_s[tid]       = fmaf(RHO, z_s[tid],       -y_s[tid]);
        w_s[tid + 256] = fmaf(RHO, z_s[tid + 256], -y_s[tid + 256]);
        __syncthreads();

        // GEMV1: partial of A^T w  (accumulate over m, float4 over j)
        float4 acc = {0.f, 0.f, 0.f, 0.f};
#pragma unroll 8
        for (int m = ms; m < MCON; m += 4)
            fma4(acc, *(const float4*)(Ab + (size_t)m*NV + jg*4), w_s[m]);
        ((float4*)red)[ms*64 + jg] = acc;
        __syncthreads();

        // rhs = sigma*x - q + A^T w
        rhs_s[tid] = fmaf(SIGMA, xs[tid], -qs[tid])
                   + red[tid] + red[256 + tid] + red[512 + tid] + red[768 + tid];
        __syncthreads();

        // GEMV2: partial of Minv * rhs  (rows 0..191 from SMEM, rest from L2)
        acc.x = acc.y = acc.z = acc.w = 0.f;
#pragma unroll 8
        for (int k = ms; k < 192; k += 4)
            fma4(acc, ((float4*)Mc)[k*64 + jg], rhs_s[k]);
#pragma unroll 4
        for (int k = 192 + ms; k < NV; k += 4)
            fma4(acc, *(const float4*)(Mb + (size_t)k*NV + jg*4), rhs_s[k]);
        __syncthreads();
        ((float4*)red)[ms*64 + jg] = acc;
        __syncthreads();

        // x~ and x update
        float xt = red[tid] + red[256 + tid] + red[512 + tid] + red[768 + tid];
        xt_s[tid] = xt;
        xs[tid] = fmaf(ALPHA, xt, (1.0f - ALPHA) * xs[tid]);
        __syncthreads();

        // GEMV3: partial of A x~ via At (accumulate over j, float4 over m)
        acc.x = acc.y = acc.z = acc.w = 0.f;
#pragma unroll 8
        for (int j = js; j < NV; j += 2)
            fma4(acc, *(const float4*)(Atb + (size_t)j*MCON + mq*4), xt_s[j]);
        ((float4*)red)[js*128 + mq] = acc;
        __syncthreads();

        // z, y updates
#pragma unroll
        for (int h = 0; h < 2; h++) {
            const int m = tid + h*256;
            float zt = red[m] + red[512 + m];
            float zr = fmaf(ALPHA, zt, (1.0f - ALPHA) * z_s[m]);
            float lo = h ? l1 : l0, hi = h ? u1 : u0;
            float zc = fminf(fmaxf(fmaf(y_s[m], 1.0f / RHO, zr), lo), hi);
            y_s[m] = fmaf(RHO, zr - zc, y_s[m]);
            z_s[m] = zc;
        }
        __syncthreads();
    }

    out[b*NV + tid] = xs[tid];
}

// ---------------------------------------------------------------------------
extern "C" void kernel_launch(void* const* d_in, const int* in_sizes, int n_in,
                              void* d_out, int out_size)
{
    const float* P = (const float*)d_in[0];
    const float* q = (const float*)d_in[1];
    const float* A = (const float*)d_in[2];
    const float* l = (const float*)d_in[3];
    const float* u = (const float*)d_in[4];
    float* out = (float*)d_out;

    const int CHOL_SMEM = 192 * 256 * 4;                 // 196608
    const int MINV_SMEM = (16384 + 16384 + 256) * 4;     // 132096
    const int ADMM_SMEM = 52736 * 4;                     // 210944
    cudaFuncSetAttribute(chol_kernel, cudaFuncAttributeMaxDynamicSharedMemorySize, CHOL_SMEM);
    cudaFuncSetAttribute(minv_kernel, cudaFuncAttributeMaxDynamicSharedMemorySize, MINV_SMEM);
    cudaFuncSetAttribute(admm_kernel, cudaFuncAttributeMaxDynamicSharedMemorySize, ADMM_SMEM);

    void *pM = nullptr, *pW = nullptr, *pAt = nullptr;
    cudaGetSymbolAddress(&pM, g_M);
    cudaGetSymbolAddress(&pW, g_W);
    cudaGetSymbolAddress(&pAt, g_At);

    syrk_kernel<<<dim3(10, NBAT), 256>>>(A, P);
    transpose_kernel<<<dim3(NV/32, MCON/32, NBAT), dim3(32, 8)>>>(A, (float*)pAt, MCON, NV);
    chol_kernel<<<NBAT, 256, CHOL_SMEM>>>();
    transpose_kernel<<<dim3(NV/32, NV/32, NBAT), dim3(32, 8)>>>((const float*)pM, (float*)pW, NV, NV);
    minv_kernel<<<dim3(4, NBAT), 256, MINV_SMEM>>>();
    admm_kernel<<<NBAT, 256, ADMM_SMEM>>>(A, q, l, u, out);
}

// round 8
// speedup vs baseline: 1.1349x; 1.1349x over previous
#include <cuda_runtime.h>

// Batched OSQP ADMM: B=64, n=256, m=512, 200 iterations.
// Launches: 1) syrk(M)+transpose(A->At)   2) Cholesky + transpose(L->g_W)
//           3) minv (blocked identity solves)  4) admm iters 0-99
//           5) noop spacer                     6) admm iters 100-199
// admm: 1 CTA/batch, 512 threads. 192 A-rows cached in SMEM with XOR swizzle,
// reused by BOTH A^T w (column-coalesced) and A x~ (row-dot). Minv + tail of
// A/At stream from L2 (entire working set L2-resident).

#define NBAT 64
#define NV   256
#define MCON 512

__device__ float g_M   [(size_t)NBAT*NV*NV];    // M, then L (col-major lower)
__device__ float g_W   [(size_t)NBAT*NV*NV];    // L row-major
__device__ float g_Minv[(size_t)NBAT*NV*NV];    // M^{-1}, row-major
__device__ float g_At  [(size_t)NBAT*NV*MCON];  // A^T: At[j*512+m]
__device__ float g_state[(size_t)NBAT*1280];    // x 256 | z 512 | y 512

__device__ __forceinline__ void fma4(float4& a, const float4 v, const float s) {
    a.x = fmaf(v.x, s, a.x); a.y = fmaf(v.y, s, a.y);
    a.z = fmaf(v.z, s, a.z); a.w = fmaf(v.w, s, a.w);
}
__device__ __forceinline__ void dot4(float4& a, const float4 v, const float4 s) {
    a.x = fmaf(v.x, s.x, a.x); a.y = fmaf(v.y, s.y, a.y);
    a.z = fmaf(v.z, s.z, a.z); a.w = fmaf(v.w, s.w, a.w);
}

// ---------------------------------------------------------------------------
// setup1: blocks [0,10) per batch: syrk  g_M = RHO*A^T A + diag(P+SIGMA)
//         blocks [10,138): 32x32 transpose tiles  A -> g_At
// ---------------------------------------------------------------------------
__global__ void __launch_bounds__(256) setup1_kernel(const float* __restrict__ A,
                                                     const float* __restrict__ P)
{
    const int pr = blockIdx.x, b = blockIdx.y;
    const int tid = threadIdx.x;

    if (pr < 10) {
        int ti, tj;
        if      (pr < 4) { ti = 0; tj = pr;     }
        else if (pr < 7) { ti = 1; tj = pr - 3; }
        else if (pr < 9) { ti = 2; tj = pr - 5; }
        else             { ti = 3; tj = 3;      }

        __shared__ float As[16 * 64], Bs[16 * 64];
        const float* Ab = A + (size_t)b * MCON * NV;
        const int lr = tid >> 4, lc = tid & 15;

        float acc[4][4] = {};
        for (int k0 = 0; k0 < MCON; k0 += 16) {
            *(float4*)(As + lr*64 + lc*4) = *(const float4*)(Ab + (size_t)(k0+lr)*NV + ti*64 + lc*4);
            *(float4*)(Bs + lr*64 + lc*4) = *(const float4*)(Ab + (size_t)(k0+lr)*NV + tj*64 + lc*4);
            __syncthreads();
#pragma unroll
            for (int kk = 0; kk < 16; kk++) {
                float4 a4 = *(float4*)(As + kk*64 + lr*4);
                float4 b4 = *(float4*)(Bs + kk*64 + lc*4);
                float av[4] = {a4.x, a4.y, a4.z, a4.w};
                float bv[4] = {b4.x, b4.y, b4.z, b4.w};
#pragma unroll
                for (int r = 0; r < 4; r++)
#pragma unroll
                    for (int s = 0; s < 4; s++)
                        acc[r][s] = fmaf(av[r], bv[s], acc[r][s]);
            }
            __syncthreads();
        }

        float* Mb = g_M + (size_t)b * NV * NV;
        const float RHO = 0.1f, SIGMA = 1e-6f;
#pragma unroll
        for (int r = 0; r < 4; r++)
#pragma unroll
            for (int s = 0; s < 4; s++) {
                int i = ti*64 + lr*4 + r;
                int j = tj*64 + lc*4 + s;
                float v = RHO * acc[r][s];
                if (i == j) v += P[b*NV + i] + SIGMA;
                Mb[(size_t)i*NV + j] = v;
                if (ti != tj) Mb[(size_t)j*NV + i] = v;
            }
    } else {
        __shared__ float t[32][33];
        const int tt = pr - 10;              // 0..127
        const int bx = tt & 7, by = tt >> 3; // col-tile over NV, row-tile over MCON
        const size_t off = (size_t)b * MCON * NV;
        const int c0 = bx * 32, r0 = by * 32;
        const int tx = tid & 31, ty = tid >> 5;  // 32 x 8
#pragma unroll
        for (int k = 0; k < 32; k += 8)
            t[ty + k][tx] = A[off + (size_t)(r0 + ty + k) * NV + c0 + tx];
        __syncthreads();
#pragma unroll
        for (int k = 0; k < 32; k += 8)
            g_At[off + (size_t)(c0 + ty + k) * MCON + r0 + tx] = t[tx][ty + k];
    }
}

// ---------------------------------------------------------------------------
// setup2: Cholesky (left-looking, col-major in g_M rows), then write g_W = L
// row-major from the smem column cache (cols >=192 gathered from g_M).
// ---------------------------------------------------------------------------
__global__ void __launch_bounds__(256) setup2_kernel()
{
    const int b = blockIdx.x, tid = threadIdx.x;
    float* M = g_M + (size_t)b * NV * NV;
    extern __shared__ float Lc[];      // 192*256 floats
    __shared__ float sdiag;

    for (int j = 0; j < NV; j++) {
        float acc = M[(size_t)j*NV + tid];
        const int kc = j < 192 ? j : 192;
#pragma unroll 4
        for (int k = 0; k < kc; k++)
            acc -= Lc[k*NV + tid] * Lc[k*NV + j];
        for (int k = 192; k < j; k++)
            acc -= M[(size_t)k*NV + tid] * M[(size_t)k*NV + j];
        if (tid == j) sdiag = acc;
        __syncthreads();
        float val = acc * rsqrtf(sdiag);
        if (tid >= j) {
            M[(size_t)j*NV + tid] = val;
            if (j < 192) Lc[j*NV + tid] = val;
        }
        __syncthreads();
    }

    // g_W[i][k] = L[i][k]  (k = tid; entries k > i are unused garbage downstream)
    float* W = g_W + (size_t)b * NV * NV;
    for (int i = 0; i < NV; i++) {
        float v = (tid < 192) ? Lc[tid*NV + i] : M[(size_t)tid*NV + i];
        W[(size_t)i*NV + tid] = v;
    }
}

// ---------------------------------------------------------------------------
// minv: block (g, b) computes 64 columns of M^{-1}. 512 threads.
// ---------------------------------------------------------------------------
__global__ void __launch_bounds__(512) minv_kernel()
{
    const int g = blockIdx.x, b = blockIdx.y, tid = threadIdx.x;
    const int c0 = g * 64;
    extern __shared__ float sm[];
    float* Yf    = sm;            // 16384
    float* Lp    = sm + 16384;    // 16384
    float* rdiag = sm + 32768;    // 256
    const float* M  = g_M + (size_t)b * NV * NV;
    const float* Wt = g_W + (size_t)b * NV * NV;

    if (tid < NV) rdiag[tid] = 1.0f / M[(size_t)tid*NV + tid];
    for (int idx = tid; idx < 16384; idx += 512) Yf[idx] = 0.0f;
    __syncthreads();
    if (tid < 64) Yf[(c0 + tid)*64 + tid] = 1.0f;
    __syncthreads();

    const int q16 = tid >> 5, c2 = tid & 31;
    float2* Y2 = (float2*)Yf;

    // forward: L y = e
    for (int i = c0; i < NV; i++) {
        if ((i & 63) == 0) {
            for (int idx = tid; idx < 16384; idx += 512)
                Lp[idx] = M[(size_t)(i + (idx >> 8)) * NV + (idx & 255)];
            __syncthreads();
        }
        if (tid < 64) Yf[i*64 + tid] *= rdiag[i];
        __syncthreads();
        float2 yv = Y2[i*32 + c2];
        const float* lcol = Lp + (i - (i & ~63)) * NV;
        for (int i2 = i + 1 + ((q16 - (i + 1)) & 15); i2 < NV; i2 += 16) {
            float lv = lcol[i2];
            float2 t = Y2[i2*32 + c2];
            t.x = fmaf(-lv, yv.x, t.x);
            t.y = fmaf(-lv, yv.y, t.y);
            Y2[i2*32 + c2] = t;
        }
        __syncthreads();
    }

    // backward: L^T x = y
    for (int i = NV - 1; i >= 0; i--) {
        if ((i & 63) == 63) {
            const int p = i - 63;
            for (int idx = tid; idx < 16384; idx += 512)
                Lp[idx] = Wt[(size_t)(p + (idx >> 8)) * NV + (idx & 255)];
            __syncthreads();
        }
        if (tid < 64) Yf[i*64 + tid] *= rdiag[i];
        __syncthreads();
        float2 xv = Y2[i*32 + c2];
        const float* lrow = Lp + (i - (i & ~63)) * NV;
        for (int i2 = q16; i2 < i; i2 += 16) {
            float lv = lrow[i2];
            float2 t = Y2[i2*32 + c2];
            t.x = fmaf(-lv, xv.x, t.x);
            t.y = fmaf(-lv, xv.y, t.y);
            Y2[i2*32 + c2] = t;
        }
        __syncthreads();
    }

    float* Mi = g_Minv + (size_t)b * NV * NV;
    for (int idx = tid; idx < 16384; idx += 512)
        Mi[(size_t)(idx >> 6) * NV + c0 + (idx & 63)] = Yf[idx];
}

__global__ void noop_kernel() {}

// ---------------------------------------------------------------------------
// admm: 1 CTA/batch, 512 threads, 100 iterations per launch (phase 0/1).
// SMEM: A rows [0,192) swizzled + state + reduction buffers (220672 B).
// z, y live in registers (one constraint per thread); x in SMEM.
// ---------------------------------------------------------------------------
__global__ void __launch_bounds__(512, 1) admm_kernel(const float* __restrict__ A,
                                                      const float* __restrict__ q,
                                                      const float* __restrict__ l,
                                                      const float* __restrict__ u,
                                                      float* __restrict__ out,
                                                      int phase)
{
    const int b = blockIdx.x, tid = threadIdx.x;
    extern __shared__ float sh[];
    float* A_s   = sh;            // 49152 (192 rows x 64 float4, swizzled)
    float* w_s   = sh + 49152;    // 512
    float* rhs_s = sh + 49664;    // 256
    float* xt_s  = sh + 49920;    // 256
    float* xs    = sh + 50176;    // 256
    float* qs    = sh + 50432;    // 256
    float* zt    = sh + 50688;    // 512
    float* red   = sh + 51200;    // 2048
    float* red2  = sh + 53248;    // 1920   -> total 55168 floats = 220672 B

    const float SIGMA = 1e-6f, RHO = 0.1f, ALPHA = 1.6f;
    const float4* A4g = (const float4*)(A      + (size_t)b * MCON * NV);
    const float4* At4 = (const float4*)(g_At   + (size_t)b * NV * MCON);
    const float4* Mi4 = (const float4*)(g_Minv + (size_t)b * NV * NV);
    float4* As4   = (float4*)A_s;
    float4* red4  = (float4*)red;
    float4* red24 = (float4*)red2;
    const float4* xt4 = (const float4*)xt_s;

    // Load A rows [0,192) into SMEM, float4-swizzled: (m,k4) -> m*64 + (k4^(m&7))
    for (int i4 = tid; i4 < 192*64; i4 += 512) {
        const int m = i4 >> 6, k4 = i4 & 63;
        As4[m*64 + (k4 ^ (m & 7))] = A4g[i4];
    }

    float z_r, y_r;
    const float l_r = l[b*MCON + tid], u_r = u[b*MCON + tid];
    float* st = g_state + (size_t)b * 1280;
    if (phase == 0) { z_r = 0.0f; y_r = 0.0f; }
    else            { z_r = st[256 + tid]; y_r = st[768 + tid]; }
    if (tid < NV) {
        qs[tid] = q[b*NV + tid];
        xs[tid] = (phase == 0) ? 0.0f : st[tid];
    }
    __syncthreads();

    const int ms = tid >> 6, jg = tid & 63;          // GEMV1/2 map (8 x 64)
    const int jx = jg ^ ms;                          // swizzled col (m%8 == ms)
    const int js = tid / 80, mq = tid - js * 80;     // GEMV3a map (6 x 80)
    const int swz = tid & 7;                         // GEMV3b row swizzle

    for (int it = 0; it < 100; it++) {
        // w = rho*z - y   (one constraint per thread)
        w_s[tid] = fmaf(RHO, z_r, -y_r);
        __syncthreads();

        // GEMV1: partials of A^T w  (rows <192 from SMEM, rest from L2)
        float4 acc = {0.f, 0.f, 0.f, 0.f};
#pragma unroll
        for (int m = ms; m < 192; m += 8)
            fma4(acc, As4[m*64 + jx], w_s[m]);
#pragma unroll 8
        for (int m = 192 + ms; m < MCON; m += 8)
            fma4(acc, A4g[m*64 + jg], w_s[m]);
        red4[ms*64 + jg] = acc;
        __syncthreads();

        // rhs = sigma*x - q + A^T w
        if (tid < NV) {
            float r = fmaf(SIGMA, xs[tid], -qs[tid]);
#pragma unroll
            for (int s = 0; s < 8; s++) r += red[s*256 + tid];
            rhs_s[tid] = r;
        }
        __syncthreads();

        // GEMV2: partials of Minv * rhs  (L2)
        acc.x = acc.y = acc.z = acc.w = 0.f;
#pragma unroll 8
        for (int k = ms; k < NV; k += 8)
            fma4(acc, Mi4[k*64 + jg], rhs_s[k]);
        red4[ms*64 + jg] = acc;
        __syncthreads();

        // x~ and x update
        if (tid < NV) {
            float xt = 0.f;
#pragma unroll
            for (int s = 0; s < 8; s++) xt += red[s*256 + tid];
            xt_s[tid] = xt;
            xs[tid] = fmaf(ALPHA, xt, (1.0f - ALPHA) * xs[tid]);
        }
        __syncthreads();

        // GEMV3a: z~[192..511] partials via At (L2), m4 = 48 + mq
        if (js < 6) {
            acc.x = acc.y = acc.z = acc.w = 0.f;
#pragma unroll 8
            for (int j = js; j < NV; j += 6)
                fma4(acc, At4[j*128 + 48 + mq], xt_s[j]);
            red24[js*80 + mq] = acc;
        }
        // GEMV3b: z~[0..191] row-dots from SMEM (A swizzled read, xt broadcast)
        if (tid < 192) {
            float4 a0 = {0.f,0.f,0.f,0.f}, a1 = {0.f,0.f,0.f,0.f};
#pragma unroll
            for (int k4 = 0; k4 < 64; k4 += 2) {
                dot4(a0, As4[tid*64 + (k4 ^ swz)], xt4[k4]);
                dot4(a1, As4[tid*64 + ((k4+1) ^ swz)], xt4[k4+1]);
            }
            zt[tid] = (a0.x + a0.y) + (a0.z + a0.w) + (a1.x + a1.y) + (a1.z + a1.w);
        }
        __syncthreads();

        // z, y updates (registers)
        float ztil;
        if (tid < 192) ztil = zt[tid];
        else {
            const int mi = tid - 192;
            ztil = red2[mi] + red2[320 + mi] + red2[640 + mi]
                 + red2[960 + mi] + red2[1280 + mi] + red2[1600 + mi];
        }
        float zr = fmaf(ALPHA, ztil, (1.0f - ALPHA) * z_r);
        float zc = fminf(fmaxf(fmaf(y_r, 10.0f, zr), l_r), u_r);  // 1/RHO = 10
        y_r = fmaf(RHO, zr - zc, y_r);
        z_r = zc;
        __syncthreads();
    }

    if (phase == 0) {
        st[256 + tid] = z_r;
        st[768 + tid] = y_r;
        if (tid < NV) st[tid] = xs[tid];
    } else {
        if (tid < NV) out[b*NV + tid] = xs[tid];
    }
}

// ---------------------------------------------------------------------------
extern "C" void kernel_launch(void* const* d_in, const int* in_sizes, int n_in,
                              void* d_out, int out_size)
{
    const float* P = (const float*)d_in[0];
    const float* q = (const float*)d_in[1];
    const float* A = (const float*)d_in[2];
    const float* l = (const float*)d_in[3];
    const float* u = (const float*)d_in[4];
    float* out = (float*)d_out;

    const int CHOL_SMEM = 192 * 256 * 4;                 // 196608
    const int MINV_SMEM = (16384 + 16384 + 256) * 4;     // 132096
    const int ADMM_SMEM = 55168 * 4;                     // 220672
    cudaFuncSetAttribute(setup2_kernel, cudaFuncAttributeMaxDynamicSharedMemorySize, CHOL_SMEM);
    cudaFuncSetAttribute(minv_kernel,   cudaFuncAttributeMaxDynamicSharedMemorySize, MINV_SMEM);
    cudaFuncSetAttribute(admm_kernel,   cudaFuncAttributeMaxDynamicSharedMemorySize, ADMM_SMEM);

    setup1_kernel<<<dim3(138, NBAT), 256>>>(A, P);
    setup2_kernel<<<NBAT, 256, CHOL_SMEM>>>();
    minv_kernel<<<dim3(4, NBAT), 512, MINV_SMEM>>>();
    admm_kernel<<<NBAT, 512, ADMM_SMEM>>>(A, q, l, u, out, 0);
    noop_kernel<<<1, 32>>>();
    admm_kernel<<<NBAT, 512, ADMM_SMEM>>>(A, q, l, u, out, 1);
}

// round 9
// speedup vs baseline: 1.2015x; 1.0587x over previous
#include <cuda_runtime.h>

// Batched OSQP ADMM: B=64, n=256, m=512, 200 iterations.
// setup1: syrk (M = rho*A'A + diag(P)+sigma) + transpose A -> g_At
// setup2: Cholesky (1024 thr, 4-way k-split) + conflict-free L -> g_W
// minv:   2 blocks/batch x 1024 thr, blocked identity solves -> g_Minv
// admm:   1 CTA/batch, 1024 threads, 100 iters/launch (2 phases).
//         192 A-rows in SMEM, Minv/At/A-tail streamed via __ldcg with
//         cross-barrier register prefetch. 6 barriers/iter, uniform work.

#define NBAT 64
#define NV   256
#define MCON 512

__device__ float g_M   [(size_t)NBAT*NV*NV];    // M, then L (col-major lower)
__device__ float g_W   [(size_t)NBAT*NV*NV];    // L row-major
__device__ float g_Minv[(size_t)NBAT*NV*NV];    // M^{-1}, row-major
__device__ float g_At  [(size_t)NBAT*NV*MCON];  // A^T: At[j*512+m]
__device__ float g_state[(size_t)NBAT*1280];    // x 256 | z 512 | y 512

__device__ __forceinline__ void fma4(float4& a, const float4 v, const float s) {
    a.x = fmaf(v.x, s, a.x); a.y = fmaf(v.y, s, a.y);
    a.z = fmaf(v.z, s, a.z); a.w = fmaf(v.w, s, a.w);
}

// ---------------------------------------------------------------------------
// setup1: blocks [0,10): syrk 64x64 tile pairs. blocks [10,138): A->At tiles.
// ---------------------------------------------------------------------------
__global__ void __launch_bounds__(256) setup1_kernel(const float* __restrict__ A,
                                                     const float* __restrict__ P)
{
    const int pr = blockIdx.x, b = blockIdx.y;
    const int tid = threadIdx.x;

    if (pr < 10) {
        int ti, tj;
        if      (pr < 4) { ti = 0; tj = pr;     }
        else if (pr < 7) { ti = 1; tj = pr - 3; }
        else if (pr < 9) { ti = 2; tj = pr - 5; }
        else             { ti = 3; tj = 3;      }

        __shared__ float As[16 * 64], Bs[16 * 64];
        const float* Ab = A + (size_t)b * MCON * NV;
        const int lr = tid >> 4, lc = tid & 15;

        float acc[4][4] = {};
        for (int k0 = 0; k0 < MCON; k0 += 16) {
            *(float4*)(As + lr*64 + lc*4) = *(const float4*)(Ab + (size_t)(k0+lr)*NV + ti*64 + lc*4);
            *(float4*)(Bs + lr*64 + lc*4) = *(const float4*)(Ab + (size_t)(k0+lr)*NV + tj*64 + lc*4);
            __syncthreads();
#pragma unroll
            for (int kk = 0; kk < 16; kk++) {
                float4 a4 = *(float4*)(As + kk*64 + lr*4);
                float4 b4 = *(float4*)(Bs + kk*64 + lc*4);
                float av[4] = {a4.x, a4.y, a4.z, a4.w};
                float bv[4] = {b4.x, b4.y, b4.z, b4.w};
#pragma unroll
                for (int r = 0; r < 4; r++)
#pragma unroll
                    for (int s = 0; s < 4; s++)
                        acc[r][s] = fmaf(av[r], bv[s], acc[r][s]);
            }
            __syncthreads();
        }

        float* Mb = g_M + (size_t)b * NV * NV;
        const float RHO = 0.1f, SIGMA = 1e-6f;
#pragma unroll
        for (int r = 0; r < 4; r++)
#pragma unroll
            for (int s = 0; s < 4; s++) {
                int i = ti*64 + lr*4 + r;
                int j = tj*64 + lc*4 + s;
                float v = RHO * acc[r][s];
                if (i == j) v += P[b*NV + i] + SIGMA;
                Mb[(size_t)i*NV + j] = v;
                if (ti != tj) Mb[(size_t)j*NV + i] = v;
            }
    } else {
        __shared__ float t[32][33];
        const int tt = pr - 10;
        const int bx = tt & 7, by = tt >> 3;
        const size_t off = (size_t)b * MCON * NV;
        const int c0 = bx * 32, r0 = by * 32;
        const int tx = tid & 31, ty = tid >> 5;
#pragma unroll
        for (int k = 0; k < 32; k += 8)
            t[ty + k][tx] = A[off + (size_t)(r0 + ty + k) * NV + c0 + tx];
        __syncthreads();
#pragma unroll
        for (int k = 0; k < 32; k += 8)
            g_At[off + (size_t)(c0 + ty + k) * MCON + r0 + tx] = t[tx][ty + k];
    }
}

// ---------------------------------------------------------------------------
// setup2: Cholesky, 1024 threads, 4-way k-split. L stored col-major in g_M
// rows; first 192 columns cached in SMEM. Then g_W = L row-major via
// conflict-free 32x32 tile transposes.
// ---------------------------------------------------------------------------
__global__ void __launch_bounds__(1024) setup2_kernel()
{
    const int b = blockIdx.x, tid = threadIdx.x;
    const int r = tid & 255, s = tid >> 8;       // 4 k-slices
    float* M = g_M + (size_t)b * NV * NV;
    extern __shared__ float Lc[];                // 192*256
    __shared__ float psum[1024];
    __shared__ float st[32][33];
    __shared__ float sdiag;

    for (int j = 0; j < NV; j++) {
        float acc = 0.0f;
        const int kc = j < 192 ? j : 192;
#pragma unroll 4
        for (int k = s; k < kc; k += 4)
            acc -= Lc[k*NV + r] * Lc[k*NV + j];
        for (int k = 192 + s; k < j; k += 4)
            acc -= M[(size_t)k*NV + r] * M[(size_t)k*NV + j];
        psum[tid] = acc;
        __syncthreads();
        float a = 0.0f;
        if (s == 0) {
            a = M[(size_t)j*NV + r] + psum[r] + psum[r+256] + psum[r+512] + psum[r+768];
            if (r == j) sdiag = a;
        }
        __syncthreads();
        if (s == 0 && r >= j) {
            float val = a * rsqrtf(sdiag);
            M[(size_t)j*NV + r] = val;
            if (j < 192) Lc[j*NV + r] = val;
        }
        __syncthreads();
    }

    // g_W[i][k] = L[i][k] via tiled transpose (conflict-free reads/writes)
    float* W = g_W + (size_t)b * NV * NV;
    const int ty = tid >> 5, tx = tid & 31;      // 32 x 32
    for (int k0 = 0; k0 < NV; k0 += 32) {
        for (int i0 = 0; i0 < NV; i0 += 32) {
            st[ty][tx] = (k0 + ty < 192) ? Lc[(k0+ty)*NV + i0 + tx]
                                         : M[(size_t)(k0+ty)*NV + i0 + tx];
            __syncthreads();
            W[(size_t)(i0+ty)*NV + k0 + tx] = st[tx][ty];
            __syncthreads();
        }
    }
}

// ---------------------------------------------------------------------------
// minv: block (g, b) computes 128 columns [g*128, g*128+128) of M^{-1}.
// 1024 threads, 128 blocks total = 1 wave.
// ---------------------------------------------------------------------------
__global__ void __launch_bounds__(1024) minv_kernel()
{
    const int g = blockIdx.x, b = blockIdx.y, tid = threadIdx.x;
    const int c0 = g * 128;
    extern __shared__ float sm[];
    float* Yf    = sm;            // 256*128 = 32768
    float* Lp    = sm + 32768;    // 64*256  = 16384
    float* rdiag = sm + 49152;    // 256
    const float* M  = g_M + (size_t)b * NV * NV;
    const float* Wt = g_W + (size_t)b * NV * NV;

    if (tid < NV) rdiag[tid] = 1.0f / M[(size_t)tid*NV + tid];
    for (int idx = tid; idx < 32768; idx += 1024) Yf[idx] = 0.0f;
    __syncthreads();
    if (tid < 128) Yf[(c0 + tid)*128 + tid] = 1.0f;
    __syncthreads();

    const int q = tid >> 6, c2 = tid & 63;       // 16 row-groups x 64 float2-cols
    float2* Y2 = (float2*)Yf;

    // forward: L y = e  (rows < c0 are zero for this block's columns)
    for (int i = c0; i < NV; i++) {
        if ((i & 63) == 0) {
            for (int idx = tid; idx < 16384; idx += 1024)
                Lp[idx] = M[(size_t)(i + (idx >> 8)) * NV + (idx & 255)];
            __syncthreads();
        }
        if (tid < 128) Yf[i*128 + tid] *= rdiag[i];
        __syncthreads();
        float2 yv = Y2[i*64 + c2];
        const float* lcol = Lp + (i & 63) * NV;
        for (int i2 = i + 1 + ((q - (i + 1)) & 15); i2 < NV; i2 += 16) {
            float lv = lcol[i2];
            float2 t = Y2[i2*64 + c2];
            t.x = fmaf(-lv, yv.x, t.x);
            t.y = fmaf(-lv, yv.y, t.y);
            Y2[i2*64 + c2] = t;
        }
        __syncthreads();
    }

    // backward: L^T x = y
    for (int i = NV - 1; i >= 0; i--) {
        if ((i & 63) == 63) {
            const int p = i - 63;
            for (int idx = tid; idx < 16384; idx += 1024)
                Lp[idx] = Wt[(size_t)(p + (idx >> 8)) * NV + (idx & 255)];
            __syncthreads();
        }
        if (tid < 128) Yf[i*128 + tid] *= rdiag[i];
        __syncthreads();
        float2 xv = Y2[i*64 + c2];
        const float* lrow = Lp + (i & 63) * NV;
        for (int i2 = q; i2 < i; i2 += 16) {
            float lv = lrow[i2];
            float2 t = Y2[i2*64 + c2];
            t.x = fmaf(-lv, xv.x, t.x);
            t.y = fmaf(-lv, xv.y, t.y);
            Y2[i2*64 + c2] = t;
        }
        __syncthreads();
    }

    float* Mi = g_Minv + (size_t)b * NV * NV;
    for (int idx = tid; idx < 32768; idx += 1024)
        Mi[(size_t)(idx >> 7) * NV + c0 + (idx & 127)] = Yf[idx];
}

__global__ void noop_kernel() {}

// ---------------------------------------------------------------------------
// admm: 1 CTA/batch, 1024 threads, 100 iterations per launch.
// ---------------------------------------------------------------------------
__global__ void __launch_bounds__(1024, 1) admm_kernel(const float* __restrict__ A,
                                                       const float* __restrict__ q,
                                                       const float* __restrict__ l,
                                                       const float* __restrict__ u,
                                                       float* __restrict__ out,
                                                       int phase)
{
    const int b = blockIdx.x, tid = threadIdx.x;
    extern __shared__ float sh[];
    float* A_s   = sh;            // 49152 (192 rows x 64 float4, linear)
    float* red   = sh + 49152;    // 4096
    float* w_s   = sh + 53248;    // 512
    float* rhs_s = sh + 53760;    // 256
    float* xt_s  = sh + 54016;    // 256
    float* xs    = sh + 54272;    // 256
    float* qs    = sh + 54528;    // 256  -> 54784 floats = 219136 B

    const float SIGMA = 1e-6f, RHO = 0.1f, ALPHA = 1.6f;
    const float4* A4g = (const float4*)(A      + (size_t)b * MCON * NV);
    const float4* At4 = (const float4*)(g_At   + (size_t)b * NV * MCON);
    const float4* Mi4 = (const float4*)(g_Minv + (size_t)b * NV * NV);
    float4* As4  = (float4*)A_s;
    float4* red4 = (float4*)red;

    // A rows [0,192) -> SMEM
    for (int i4 = tid; i4 < 192*64; i4 += 1024)
        As4[i4] = A4g[i4];

    float z_r = 0.0f, y_r = 0.0f, l_r = 0.0f, u_r = 0.0f;
    float* st = g_state + (size_t)b * 1280;
    if (tid < MCON) {
        l_r = l[b*MCON + tid]; u_r = u[b*MCON + tid];
        if (phase) { z_r = st[256 + tid]; y_r = st[768 + tid]; }
        w_s[tid] = fmaf(RHO, z_r, -y_r);
    }
    if (tid < NV) {
        qs[tid] = q[b*NV + tid];
        xs[tid] = phase ? st[tid] : 0.0f;
    }
    __syncthreads();

    const int ms = tid >> 6, jg = tid & 63;      // 16 x 64 (GEMV1/2)
    const int js = tid >> 7, mq = tid & 127;     // 8 x 128 (GEMV3)

    for (int it = 0; it < 100; it++) {
        // ---- GEMV1: A^T w  (L2 tail first, then SMEM rows) ----
        float4 acc = {0.f, 0.f, 0.f, 0.f};
#pragma unroll 4
        for (int m = 192 + ms; m < MCON; m += 16)         // 20 iters
            fma4(acc, __ldcg(A4g + m*64 + jg), w_s[m]);
#pragma unroll 4
        for (int m = ms; m < 192; m += 16)                // 12 iters
            fma4(acc, As4[m*64 + jg], w_s[m]);
        red4[ms*64 + jg] = acc;
        // prefetch Minv (addresses independent of rhs)
        float4 p0 = __ldcg(Mi4 + (ms     )*64 + jg);
        float4 p1 = __ldcg(Mi4 + (ms + 16)*64 + jg);
        float4 p2 = __ldcg(Mi4 + (ms + 32)*64 + jg);
        float4 p3 = __ldcg(Mi4 + (ms + 48)*64 + jg);
        __syncthreads();                                   // S1

        // ---- rhs = sigma*x - q + A^T w ----
        if (tid < NV) {
            float r = fmaf(SIGMA, xs[tid], -qs[tid]);
#pragma unroll
            for (int s = 0; s < 16; s++) r += red[s*256 + tid];
            rhs_s[tid] = r;
        }
        __syncthreads();                                   // S2

        // ---- GEMV2: Minv * rhs ----
        acc.x = acc.y = acc.z = acc.w = 0.f;
        fma4(acc, p0, rhs_s[ms]);
        fma4(acc, p1, rhs_s[ms + 16]);
        fma4(acc, p2, rhs_s[ms + 32]);
        fma4(acc, p3, rhs_s[ms + 48]);
#pragma unroll 4
        for (int k = ms + 64; k < NV; k += 16)            // 12 iters
            fma4(acc, __ldcg(Mi4 + k*64 + jg), rhs_s[k]);
        red4[ms*64 + jg] = acc;
        // prefetch At (addresses independent of x~)
        float4 q0 = __ldcg(At4 + (js     )*128 + mq);
        float4 q1 = __ldcg(At4 + (js +  8)*128 + mq);
        float4 q2 = __ldcg(At4 + (js + 16)*128 + mq);
        float4 q3 = __ldcg(At4 + (js + 24)*128 + mq);
        __syncthreads();                                   // S3

        // ---- x~ and x update ----
        if (tid < NV) {
            float xt = 0.f;
#pragma unroll
            for (int s = 0; s < 16; s++) xt += red[s*256 + tid];
            xt_s[tid] = xt;
            xs[tid] = fmaf(ALPHA, xt, (1.0f - ALPHA) * xs[tid]);
        }
        __syncthreads();                                   // S4

        // ---- GEMV3: A x~ via At ----
        acc.x = acc.y = acc.z = acc.w = 0.f;
        fma4(acc, q0, xt_s[js]);
        fma4(acc, q1, xt_s[js +  8]);
        fma4(acc, q2, xt_s[js + 16]);
        fma4(acc, q3, xt_s[js + 24]);
#pragma unroll 4
        for (int j = js + 32; j < NV; j += 8)             // 28 iters
            fma4(acc, __ldcg(At4 + j*128 + mq), xt_s[j]);
        red4[js*128 + mq] = acc;
        __syncthreads();                                   // S5

        // ---- z, y updates + next w ----
        if (tid < MCON) {
            float ztil = 0.f;
#pragma unroll
            for (int s = 0; s < 8; s++) ztil += red[s*512 + tid];
            float zr = fmaf(ALPHA, ztil, (1.0f - ALPHA) * z_r);
            float zc = fminf(fmaxf(fmaf(y_r, 10.0f, zr), l_r), u_r);  // 1/RHO=10
            y_r = fmaf(RHO, zr - zc, y_r);
            z_r = zc;
            w_s[tid] = fmaf(RHO, z_r, -y_r);
        }
        __syncthreads();                                   // S6
    }

    if (phase == 0) {
        if (tid < MCON) { st[256 + tid] = z_r; st[768 + tid] = y_r; }
        if (tid < NV)   st[tid] = xs[tid];
    } else {
        if (tid < NV) out[b*NV + tid] = xs[tid];
    }
}

// ---------------------------------------------------------------------------
extern "C" void kernel_launch(void* const* d_in, const int* in_sizes, int n_in,
                              void* d_out, int out_size)
{
    const float* P = (const float*)d_in[0];
    const float* q = (const float*)d_in[1];
    const float* A = (const float*)d_in[2];
    const float* l = (const float*)d_in[3];
    const float* u = (const float*)d_in[4];
    float* out = (float*)d_out;

    const int CHOL_SMEM = 192 * 256 * 4;                 // 196608
    const int MINV_SMEM = (32768 + 16384 + 256) * 4;     // 197632
    const int ADMM_SMEM = 54784 * 4;                     // 219136
    cudaFuncSetAttribute(setup2_kernel, cudaFuncAttributeMaxDynamicSharedMemorySize, CHOL_SMEM);
    cudaFuncSetAttribute(minv_kernel,   cudaFuncAttributeMaxDynamicSharedMemorySize, MINV_SMEM);
    cudaFuncSetAttribute(admm_kernel,   cudaFuncAttributeMaxDynamicSharedMemorySize, ADMM_SMEM);

    setup1_kernel<<<dim3(138, NBAT), 256>>>(A, P);
    setup2_kernel<<<NBAT, 1024, CHOL_SMEM>>>();
    minv_kernel<<<dim3(2, NBAT), 1024, MINV_SMEM>>>();
    admm_kernel<<<NBAT, 1024, ADMM_SMEM>>>(A, q, l, u, out, 0);
    noop_kernel<<<1, 32>>>();
    admm_kernel<<<NBAT, 1024, ADMM_SMEM>>>(A, q, l, u, out, 1);
}